// round 3
// baseline (speedup 1.0000x reference)
#include <cuda_runtime.h>

// Problem constants
#define BB   32
#define DD   256
#define HH   64
#define WW   64
#define CO   384   // 64 q + 256 v + 64 k
#define EPS  1e-5f

typedef unsigned long long u64;

__device__ __forceinline__ u64 pack2(float lo, float hi) {
    u64 r; asm("mov.b64 %0, {%1, %2};" : "=l"(r) : "f"(lo), "f"(hi)); return r;
}
__device__ __forceinline__ void unpack2(u64 v, float& lo, float& hi) {
    asm("mov.b64 {%0, %1}, %2;" : "=f"(lo), "=f"(hi) : "l"(v));
}
__device__ __forceinline__ void fma2(u64& d, u64 a, u64 b) {
    asm("fma.rn.f32x2 %0, %1, %2, %0;" : "+l"(d) : "l"(a), "l"(b));
}

// SMEM layout (floats):
//   sW : [384][65]  (o-major, pad 65 -> conflict-free scalar weight reads)
//   sX : [64][64]   (x tile: k-chunk rows x 64 pixels)
//   sC : [64][64]   (c tile)
#define SW_STRIDE 65
#define SW_ELEMS  (CO * SW_STRIDE)          // 24960
#define SX_ELEMS  (64 * 64)
#define SMEM_FLOATS (SW_ELEMS + 2 * SX_ELEMS)
#define SMEM_BYTES  (SMEM_FLOATS * 4)       // 132,608 B

__global__ __launch_bounds__(384, 1)
void lamba_kernel(const float* __restrict__ x,  const float* __restrict__ c,
                  const float* __restrict__ Wq, const float* __restrict__ Wv,
                  const float* __restrict__ Wk,
                  const float* __restrict__ qg, const float* __restrict__ qb,
                  const float* __restrict__ qm, const float* __restrict__ qv,
                  const float* __restrict__ vg, const float* __restrict__ vb,
                  const float* __restrict__ vm, const float* __restrict__ vv,
                  float* __restrict__ out)
{
    extern __shared__ float smem[];
    float* sW = smem;
    float* sX = smem + SW_ELEMS;
    float* sC = sX + SX_ELEMS;

    const int tid = threadIdx.x;        // 0..383
    const int tn  = tid & 7;            // pixel tile 0..7
    const int tm  = tid >> 3;           // channel tile 0..47
    const int bh  = blockIdx.x;         // 0..2047
    const int b   = bh >> 6;
    const int h   = bh & 63;
    const int w0  = tn * 8;
    const int oc0 = tm * 8;

    // 8 channels x 4 pixel-pairs of packed f32x2 accumulators
    u64 acc[8][4];
    #pragma unroll
    for (int i = 0; i < 8; i++)
        #pragma unroll
        for (int p = 0; p < 4; p++) acc[i][p] = 0ULL;

    const float* src = (oc0 < 64) ? sX : sC;   // q reduces over x; v,k over c
    const int gbase = b * (DD * HH * WW) + h * WW;   // d=0 element for this (b,h)

    for (int kc = 0; kc < DD; kc += 64) {
        __syncthreads();
        // --- stage x and c tiles: 64 rows x 64 pixels each, float4 coalesced ---
        #pragma unroll
        for (int r = 0; r < 3; r++) {
            int idx = tid + r * 384;
            if (idx < 1024) {                 // 1024 float4 per tile
                int kk = idx >> 4;
                int w4 = (idx & 15) << 2;
                int g  = gbase + (kc + kk) * (HH * WW) + w4;
                *(float4*)(sX + kk * 64 + w4) = *(const float4*)(x + g);
                *(float4*)(sC + kk * 64 + w4) = *(const float4*)(c + g);
            }
        }
        // --- stage weight chunk: all 384 out-channels x 64 k, o-major ---
        #pragma unroll
        for (int r = 0; r < 16; r++) {
            int idx = tid + r * 384;          // 0..6143, exactly 6144 float4
            int o   = idx >> 4;
            int k4  = (idx & 15) << 2;
            const float* Ws; int orow;
            if (o < 64)       { Ws = Wq; orow = o; }
            else if (o < 320) { Ws = Wv; orow = o - 64; }
            else              { Ws = Wk; orow = o - 320; }
            float4 wv4 = *(const float4*)(Ws + orow * DD + kc + k4);
            sW[o * SW_STRIDE + k4 + 0] = wv4.x;
            sW[o * SW_STRIDE + k4 + 1] = wv4.y;
            sW[o * SW_STRIDE + k4 + 2] = wv4.z;
            sW[o * SW_STRIDE + k4 + 3] = wv4.w;
        }
        __syncthreads();

        // --- compute: 8ch x 8px register tile, packed f32x2 FMAs ---
        #pragma unroll 4
        for (int kk = 0; kk < 64; kk++) {
            const float* xrow = src + kk * 64 + w0;
            ulonglong2 pa = *(const ulonglong2*)(xrow);
            ulonglong2 pb = *(const ulonglong2*)(xrow + 4);
            u64 px[4] = {pa.x, pa.y, pb.x, pb.y};
            u64 wp[8];
            #pragma unroll
            for (int i = 0; i < 8; i++) {
                float w = sW[(oc0 + i) * SW_STRIDE + kk];
                wp[i] = pack2(w, w);
            }
            #pragma unroll
            for (int i = 0; i < 8; i++)
                #pragma unroll
                for (int p = 0; p < 4; p++)
                    fma2(acc[i][p], px[p], wp[i]);
        }
    }

    // --- unpack accumulators ---
    float v[8][8];
    #pragma unroll
    for (int i = 0; i < 8; i++)
        #pragma unroll
        for (int p = 0; p < 4; p++)
            unpack2(acc[i][p], v[i][2 * p], v[i][2 * p + 1]);

    const int obase = ((b * CO + oc0) * HH + h) * WW + w0;

    if (oc0 < 320) {
        // ---- q / v channels: eval-mode BatchNorm, warp-uniform branch ----
        #pragma unroll
        for (int i = 0; i < 8; i++) {
            int o = oc0 + i;
            float g, be, mn, va;
            if (o < 64) { g = qg[o];     be = qb[o];     mn = qm[o];     va = qv[o]; }
            else        { g = vg[o-64];  be = vb[o-64];  mn = vm[o-64];  va = vv[o-64]; }
            float sc = g * rsqrtf(va + EPS);
            float sh = be - mn * sc;
            float4 o0 = make_float4(v[i][0]*sc+sh, v[i][1]*sc+sh, v[i][2]*sc+sh, v[i][3]*sc+sh);
            float4 o1 = make_float4(v[i][4]*sc+sh, v[i][5]*sc+sh, v[i][6]*sc+sh, v[i][7]*sc+sh);
            *(float4*)(out + obase + i * (HH * WW))     = o0;
            *(float4*)(out + obase + i * (HH * WW) + 4) = o1;
        }
    } else {
        // ---- k channels: softmax over the 64-pixel W row ----
        // The 8 threads (tn=0..7) holding one channel row sit in one 8-lane
        // group of the warp; k-channel tiles occupy warps 10,11 entirely,
        // so the shuffles below are warp-uniform.
        #pragma unroll
        for (int i = 0; i < 8; i++) {
            float m = v[i][0];
            #pragma unroll
            for (int j = 1; j < 8; j++) m = fmaxf(m, v[i][j]);
            #pragma unroll
            for (int d = 1; d < 8; d <<= 1)
                m = fmaxf(m, __shfl_xor_sync(0xffffffffu, m, d));
            float e[8], s = 0.0f;
            #pragma unroll
            for (int j = 0; j < 8; j++) { e[j] = __expf(v[i][j] - m); s += e[j]; }
            #pragma unroll
            for (int d = 1; d < 8; d <<= 1)
                s += __shfl_xor_sync(0xffffffffu, s, d);
            float inv = __frcp_rn(s);
            float4 o0 = make_float4(e[0]*inv, e[1]*inv, e[2]*inv, e[3]*inv);
            float4 o1 = make_float4(e[4]*inv, e[5]*inv, e[6]*inv, e[7]*inv);
            *(float4*)(out + obase + i * (HH * WW))     = o0;
            *(float4*)(out + obase + i * (HH * WW) + 4) = o1;
        }
    }
}

extern "C" void kernel_launch(void* const* d_in, const int* in_sizes, int n_in,
                              void* d_out, int out_size)
{
    const float* x  = (const float*)d_in[0];
    const float* c  = (const float*)d_in[1];
    const float* Wq = (const float*)d_in[2];
    const float* Wv = (const float*)d_in[3];
    const float* Wk = (const float*)d_in[4];
    const float* qg = (const float*)d_in[5];
    const float* qb = (const float*)d_in[6];
    const float* qm = (const float*)d_in[7];
    const float* qv = (const float*)d_in[8];
    const float* vg = (const float*)d_in[9];
    const float* vb = (const float*)d_in[10];
    const float* vm = (const float*)d_in[11];
    const float* vv = (const float*)d_in[12];
    float* out = (float*)d_out;

    cudaFuncSetAttribute(lamba_kernel,
                         cudaFuncAttributeMaxDynamicSharedMemorySize, SMEM_BYTES);
    lamba_kernel<<<BB * HH, 384, SMEM_BYTES>>>(
        x, c, Wq, Wv, Wk, qg, qb, qm, qv, vg, vb, vm, vv, out);
}

// round 5
// speedup vs baseline: 3.6124x; 3.6124x over previous
#include <cuda_runtime.h>
#include <cuda_fp16.h>
#include <cstdint>

#define EPS 1e-5f

__device__ __half g_Wh[384 * 256];
__device__ float g_bnsc[384];
__device__ float g_bnsh[384];

// smem: A [128 rows][64 fp16 =128B] | Bx [64 rows][128 fp16 =256B] | Bc same
#define OFF_A  0u
#define OFF_BX 16384u
#define OFF_BC 32768u
#define SMEM_TOTAL 49152

// 128B-row swizzle (A): bits[6:4] ^= bits[9:7]
__device__ __forceinline__ uint32_t swzA(uint32_t o) { return o ^ ((o >> 3) & 0x70); }
// 256B-row swizzle (B): bits[6:4] ^= bits[10:8]
__device__ __forceinline__ uint32_t swzB(uint32_t o) { return o ^ ((o >> 4) & 0x70); }

__device__ __forceinline__ uint32_t s2u(const void* p) {
    uint32_t a;
    asm("{ .reg .u64 t; cvta.to.shared.u64 t, %1; cvt.u32.u64 %0, t; }" : "=r"(a) : "l"(p));
    return a;
}
__device__ __forceinline__ void ldsm_x4(uint32_t* r, uint32_t a) {
    asm volatile("ldmatrix.sync.aligned.m8n8.x4.shared.b16 {%0,%1,%2,%3}, [%4];"
                 : "=r"(r[0]), "=r"(r[1]), "=r"(r[2]), "=r"(r[3]) : "r"(a));
}
__device__ __forceinline__ void ldsm_x4t(uint32_t* r, uint32_t a) {
    asm volatile("ldmatrix.sync.aligned.m8n8.x4.trans.shared.b16 {%0,%1,%2,%3}, [%4];"
                 : "=r"(r[0]), "=r"(r[1]), "=r"(r[2]), "=r"(r[3]) : "r"(a));
}
__device__ __forceinline__ void mma16816(float* d, const uint32_t* a, const uint32_t* b) {
    asm volatile("mma.sync.aligned.m16n8k16.row.col.f32.f16.f16.f32 "
                 "{%0,%1,%2,%3}, {%4,%5,%6,%7}, {%8,%9}, {%0,%1,%2,%3};"
                 : "+f"(d[0]), "+f"(d[1]), "+f"(d[2]), "+f"(d[3])
                 : "r"(a[0]), "r"(a[1]), "r"(a[2]), "r"(a[3]), "r"(b[0]), "r"(b[1]));
}

// ---------------- prep: W fp32 -> fp16, fold BN ----------------
__global__ void prep_kernel(const float* __restrict__ Wq, const float* __restrict__ Wv,
                            const float* __restrict__ Wk,
                            const float* __restrict__ qg, const float* __restrict__ qb,
                            const float* __restrict__ qm, const float* __restrict__ qv,
                            const float* __restrict__ vg, const float* __restrict__ vb,
                            const float* __restrict__ vm, const float* __restrict__ vv)
{
    int idx = blockIdx.x * blockDim.x + threadIdx.x;
    int stride = gridDim.x * blockDim.x;
    for (int i = idx; i < 384 * 256; i += stride) {
        int r = i >> 8, k = i & 255;
        float w = (r < 64) ? Wq[(r << 8) | k]
                : (r < 320) ? Wv[((r - 64) << 8) | k]
                            : Wk[((r - 320) << 8) | k];
        g_Wh[i] = __float2half_rn(w);
    }
    if (idx < 384) {
        float sc = 1.f, sh = 0.f;
        if (idx < 320) {
            float g, b, m, v;
            if (idx < 64) { g = qg[idx]; b = qb[idx]; m = qm[idx]; v = qv[idx]; }
            else { g = vg[idx-64]; b = vb[idx-64]; m = vm[idx-64]; v = vv[idx-64]; }
            sc = g * rsqrtf(v + EPS);
            sh = b - m * sc;
        }
        g_bnsc[idx] = sc; g_bnsh[idx] = sh;
    }
}

// ---------------- main: fp16 HMMA GEMM + BN/softmax epilogue ----------------
__global__ __launch_bounds__(256, 2)
void main_kernel(const float* __restrict__ x, const float* __restrict__ c,
                 float* __restrict__ out)
{
    extern __shared__ char smem[];
    const uint32_t sb = s2u(smem);
    const int tid = threadIdx.x, wid = tid >> 5, lane = tid & 31;
    const int mw = wid >> 1, nw = wid & 1;          // warp grid 4(M) x 2(N)
    const int bid = blockIdx.x;
    const int mblk = bid % 3;                        // ch blocks: 0-127, 128-255, 256-383
    const int tile = bid / 3;                        // 1024 pixel tiles
    const int b = tile >> 5, pxb = (tile & 31) << 7;
    const int ch0 = mblk << 7;

    float d[2][8][4];
    #pragma unroll
    for (int mt = 0; mt < 2; mt++)
        #pragma unroll
        for (int nt = 0; nt < 8; nt++)
            d[mt][nt][0] = d[mt][nt][1] = d[mt][nt][2] = d[mt][nt][3] = 0.f;

    // q channels (block0, mw<2) reduce over x; everything else over c
    const uint32_t sbB = sb + ((mblk == 0 && mw < 2) ? OFF_BX : OFF_BC);

    for (int ck = 0; ck < 4; ck++) {
        if (ck) __syncthreads();                     // prior compute done reading smem
        const int kc = ck << 6;

        // ---- A chunk via cp.async: 128 rows x 64 fp16 (swizzled) ----
        #pragma unroll
        for (int i = 0; i < 4; i++) {
            int idx = tid + (i << 8);
            int r = idx >> 3, u = idx & 7;
            uint32_t dst = sb + OFF_A + swzA((uint32_t)((r << 7) + (u << 4)));
            const __half* gp = g_Wh + ((ch0 + r) << 8) + kc + (u << 3);
            asm volatile("cp.async.cg.shared.global [%0], [%1], 16;" :: "r"(dst), "l"(gp));
        }
        asm volatile("cp.async.commit_group;");

        // ---- B c tile: 64k x 128px fp32 -> fp16, K-major (gmem layout matches) ----
        #pragma unroll
        for (int i = 0; i < 8; i++) {
            int idx = tid + (i << 8);
            int kk = idx >> 5, q4 = idx & 31;
            float4 v = *(const float4*)(c + (size_t)((b << 8) + kc + kk) * 4096 + pxb + (q4 << 2));
            __half2 h0 = __floats2half2_rn(v.x, v.y);
            __half2 h1 = __floats2half2_rn(v.z, v.w);
            uint2 pk = make_uint2(*(uint32_t*)&h0, *(uint32_t*)&h1);
            *(uint2*)(smem + OFF_BC + swzB((uint32_t)((kk << 8) + (q4 << 3)))) = pk;
        }
        // ---- B x tile (only the q M-block needs it) ----
        if (mblk == 0) {
            #pragma unroll
            for (int i = 0; i < 8; i++) {
                int idx = tid + (i << 8);
                int kk = idx >> 5, q4 = idx & 31;
                float4 v = *(const float4*)(x + (size_t)((b << 8) + kc + kk) * 4096 + pxb + (q4 << 2));
                __half2 h0 = __floats2half2_rn(v.x, v.y);
                __half2 h1 = __floats2half2_rn(v.z, v.w);
                uint2 pk = make_uint2(*(uint32_t*)&h0, *(uint32_t*)&h1);
                *(uint2*)(smem + OFF_BX + swzB((uint32_t)((kk << 8) + (q4 << 3)))) = pk;
            }
        }
        asm volatile("cp.async.wait_group 0;");
        __syncthreads();

        // ---- compute: 4 k16 steps, warp tile 2(m16) x 8(n8) ----
        #pragma unroll
        for (int ks = 0; ks < 4; ks++) {
            uint32_t a[2][4], bf[8][2];
            #pragma unroll
            for (int mt = 0; mt < 2; mt++) {
                int row = (mw << 5) + (mt << 4) + (lane & 15);
                int kb  = (ks << 4) + ((lane >> 4) << 3);
                ldsm_x4(a[mt], sb + OFF_A + swzA((uint32_t)((row << 7) + (kb << 1))));
            }
            #pragma unroll
            for (int p = 0; p < 4; p++) {
                int krow = (ks << 4) + (lane & 15);
                int ncol = (nw << 6) + (p << 4) + ((lane >> 4) << 3);
                uint32_t r[4];
                ldsm_x4t(r, sbB + swzB((uint32_t)((krow << 8) + (ncol << 1))));
                bf[2*p][0] = r[0]; bf[2*p][1] = r[1];
                bf[2*p+1][0] = r[2]; bf[2*p+1][1] = r[3];
            }
            #pragma unroll
            for (int mt = 0; mt < 2; mt++)
                #pragma unroll
                for (int nt = 0; nt < 8; nt++)
                    mma16816(d[mt][nt], a[mt], bf[nt]);
        }
    }

    // ================= epilogue =================
    const int g = lane >> 2, cc = lane & 3;
    const bool isK = (mblk == 2 && mw >= 2);   // channels 320-383

    #pragma unroll
    for (int mt = 0; mt < 2; mt++) {
        const int chA = ch0 + (mw << 5) + (mt << 4) + g;         // rows chA, chA+8
        float* oA = out + ((size_t)b * 384 + chA) * 4096 + pxb + (nw << 6);
        float* oB = oA + (size_t)8 * 4096;
        if (!isK) {
            float s0 = g_bnsc[chA],     h0 = g_bnsh[chA];
            float s1 = g_bnsc[chA + 8], h1 = g_bnsh[chA + 8];
            #pragma unroll
            for (int nt = 0; nt < 8; nt++) {
                int col = (nt << 3) + (cc << 1);
                *(float2*)(oA + col) = make_float2(fmaf(d[mt][nt][0], s0, h0),
                                                   fmaf(d[mt][nt][1], s0, h0));
                *(float2*)(oB + col) = make_float2(fmaf(d[mt][nt][2], s1, h1),
                                                   fmaf(d[mt][nt][3], s1, h1));
            }
        } else {
            // softmax over this warp's 64 cols = one full W row; 4-thread quad owns a row
            float mx0 = -3.4e38f, mx1 = -3.4e38f;
            #pragma unroll
            for (int nt = 0; nt < 8; nt++) {
                mx0 = fmaxf(mx0, fmaxf(d[mt][nt][0], d[mt][nt][1]));
                mx1 = fmaxf(mx1, fmaxf(d[mt][nt][2], d[mt][nt][3]));
            }
            mx0 = fmaxf(mx0, __shfl_xor_sync(0xffffffffu, mx0, 1));
            mx0 = fmaxf(mx0, __shfl_xor_sync(0xffffffffu, mx0, 2));
            mx1 = fmaxf(mx1, __shfl_xor_sync(0xffffffffu, mx1, 1));
            mx1 = fmaxf(mx1, __shfl_xor_sync(0xffffffffu, mx1, 2));
            float s0 = 0.f, s1 = 0.f;
            #pragma unroll
            for (int nt = 0; nt < 8; nt++) {
                d[mt][nt][0] = __expf(d[mt][nt][0] - mx0); s0 += d[mt][nt][0];
                d[mt][nt][1] = __expf(d[mt][nt][1] - mx0); s0 += d[mt][nt][1];
                d[mt][nt][2] = __expf(d[mt][nt][2] - mx1); s1 += d[mt][nt][2];
                d[mt][nt][3] = __expf(d[mt][nt][3] - mx1); s1 += d[mt][nt][3];
            }
            s0 += __shfl_xor_sync(0xffffffffu, s0, 1);
            s0 += __shfl_xor_sync(0xffffffffu, s0, 2);
            s1 += __shfl_xor_sync(0xffffffffu, s1, 1);
            s1 += __shfl_xor_sync(0xffffffffu, s1, 2);
            float i0 = __frcp_rn(s0), i1 = __frcp_rn(s1);
            #pragma unroll
            for (int nt = 0; nt < 8; nt++) {
                int col = (nt << 3) + (cc << 1);
                *(float2*)(oA + col) = make_float2(d[mt][nt][0] * i0, d[mt][nt][1] * i0);
                *(float2*)(oB + col) = make_float2(d[mt][nt][2] * i1, d[mt][nt][3] * i1);
            }
        }
    }
}

extern "C" void kernel_launch(void* const* d_in, const int* in_sizes, int n_in,
                              void* d_out, int out_size)
{
    const float* x = (const float*)d_in[0];
    const float* c = (const float*)d_in[1];
    prep_kernel<<<96, 256>>>((const float*)d_in[2], (const float*)d_in[3],
                             (const float*)d_in[4], (const float*)d_in[5],
                             (const float*)d_in[6], (const float*)d_in[7],
                             (const float*)d_in[8], (const float*)d_in[9],
                             (const float*)d_in[10], (const float*)d_in[11],
                             (const float*)d_in[12]);
    cudaFuncSetAttribute(main_kernel, cudaFuncAttributeMaxDynamicSharedMemorySize, SMEM_TOTAL);
    main_kernel<<<3072, 256, SMEM_TOTAL>>>(x, c, (float*)d_out);
}

// round 6
// speedup vs baseline: 4.3550x; 1.2055x over previous
#include <cuda_runtime.h>
#include <cuda_fp16.h>
#include <cstdint>

#define EPS 1e-5f

__device__ __half g_Wh[384 * 256];
__device__ float g_bnsc[384];
__device__ float g_bnsh[384];

// smem byte offsets (K-chunk = 32)
#define OFF_A    0u        // A fp16: 2 bufs x 128 rows x 64B (swz64)       = 16 KB
#define OFF_B16X 16384u    // B fp16 x: 2 bufs x 32 rows x 256B (swzB)      = 16 KB
#define OFF_B16C 32768u    // B fp16 c: 2 bufs x 32 rows x 256B             = 16 KB
#define OFF_STGX 49152u    // staging fp32 x: 32 rows x 512B (single buf)   = 16 KB
#define OFF_STGC 65536u    // staging fp32 c                                 = 16 KB
#define SMEM_TOTAL 81920

// 64B-row swizzle (A tiles): bits[5:4] ^= row bits
__device__ __forceinline__ uint32_t swzA(uint32_t o) { return o ^ ((o >> 3) & 0x30); }
// 256B-row swizzle (B tiles)
__device__ __forceinline__ uint32_t swzB(uint32_t o) { return o ^ ((o >> 4) & 0x70); }

__device__ __forceinline__ uint32_t s2u(const void* p) {
    uint32_t a;
    asm("{ .reg .u64 t; cvta.to.shared.u64 t, %1; cvt.u32.u64 %0, t; }" : "=r"(a) : "l"(p));
    return a;
}
__device__ __forceinline__ void ldsm_x4(uint32_t* r, uint32_t a) {
    asm volatile("ldmatrix.sync.aligned.m8n8.x4.shared.b16 {%0,%1,%2,%3}, [%4];"
                 : "=r"(r[0]), "=r"(r[1]), "=r"(r[2]), "=r"(r[3]) : "r"(a));
}
__device__ __forceinline__ void ldsm_x4t(uint32_t* r, uint32_t a) {
    asm volatile("ldmatrix.sync.aligned.m8n8.x4.trans.shared.b16 {%0,%1,%2,%3}, [%4];"
                 : "=r"(r[0]), "=r"(r[1]), "=r"(r[2]), "=r"(r[3]) : "r"(a));
}
__device__ __forceinline__ void mma16816(float* d, const uint32_t* a, const uint32_t* b) {
    asm volatile("mma.sync.aligned.m16n8k16.row.col.f32.f16.f16.f32 "
                 "{%0,%1,%2,%3}, {%4,%5,%6,%7}, {%8,%9}, {%0,%1,%2,%3};"
                 : "+f"(d[0]), "+f"(d[1]), "+f"(d[2]), "+f"(d[3])
                 : "r"(a[0]), "r"(a[1]), "r"(a[2]), "r"(a[3]), "r"(b[0]), "r"(b[1]));
}
__device__ __forceinline__ void cpa16(uint32_t dst, const void* src) {
    asm volatile("cp.async.cg.shared.global [%0], [%1], 16;" :: "r"(dst), "l"(src));
}

// ---------------- prep: W fp32 -> fp16, fold BN ----------------
__global__ void prep_kernel(const float* __restrict__ Wq, const float* __restrict__ Wv,
                            const float* __restrict__ Wk,
                            const float* __restrict__ qg, const float* __restrict__ qb,
                            const float* __restrict__ qm, const float* __restrict__ qv,
                            const float* __restrict__ vg, const float* __restrict__ vb,
                            const float* __restrict__ vm, const float* __restrict__ vv)
{
    int idx = blockIdx.x * blockDim.x + threadIdx.x;
    int stride = gridDim.x * blockDim.x;
    for (int i = idx; i < 384 * 256; i += stride) {
        int r = i >> 8, k = i & 255;
        float w = (r < 64) ? Wq[(r << 8) | k]
                : (r < 320) ? Wv[((r - 64) << 8) | k]
                            : Wk[((r - 320) << 8) | k];
        g_Wh[i] = __float2half_rn(w);
    }
    if (idx < 384) {
        float sc = 1.f, sh = 0.f;
        if (idx < 320) {
            float g, b, m, v;
            if (idx < 64) { g = qg[idx]; b = qb[idx]; m = qm[idx]; v = qv[idx]; }
            else { g = vg[idx-64]; b = vb[idx-64]; m = vm[idx-64]; v = vv[idx-64]; }
            sc = g * rsqrtf(v + EPS);
            sh = b - m * sc;
        }
        g_bnsc[idx] = sc; g_bnsh[idx] = sh;
    }
}

// ---------------- main: pipelined fp16 HMMA GEMM ----------------
__global__ __launch_bounds__(256, 2)
void main_kernel(const float* __restrict__ x, const float* __restrict__ c,
                 float* __restrict__ out)
{
    extern __shared__ char smem[];
    const uint32_t sb = s2u(smem);
    const int tid = threadIdx.x, wid = tid >> 5, lane = tid & 31;
    const int mw = wid >> 1, nw = wid & 1;           // warp grid 4(M) x 2(N)
    const int bid = blockIdx.x;
    const int mblk = bid % 3;                        // ch blocks 0-127 / 128-255 / 256-383
    const int tile = bid / 3;
    const int b = tile >> 5, pxb = (tile & 31) << 7;
    const int ch0 = mblk << 7;

    float d[2][8][4];
    #pragma unroll
    for (int mt = 0; mt < 2; mt++)
        #pragma unroll
        for (int nt = 0; nt < 8; nt++)
            d[mt][nt][0] = d[mt][nt][1] = d[mt][nt][2] = d[mt][nt][3] = 0.f;

    const bool needX = (mblk == 0);
    // q channels (block0, mw<2) reduce over x; everything else over c
    const uint32_t offB = (mblk == 0 && mw < 2) ? OFF_B16X : OFF_B16C;

    // ---- async issue of chunk ck: A fp16 + fp32 staging of B ----
    auto issue = [&](int ck) {
        const int kc = ck << 5;
        const uint32_t abuf = sb + OFF_A + ((ck & 1) << 13);
        #pragma unroll
        for (int i = 0; i < 2; i++) {                // A: 512 granules
            int idx = tid + (i << 8);
            int r = idx >> 2, u = idx & 3;
            cpa16(abuf + swzA((uint32_t)((r << 6) + (u << 4))),
                  g_Wh + ((ch0 + r) << 8) + kc + (u << 3));
        }
        #pragma unroll
        for (int i = 0; i < 4; i++) {                // staging c: 1024 granules
            int idx = tid + (i << 8);
            int kk = idx >> 5, p = idx & 31;
            cpa16(sb + OFF_STGC + (uint32_t)((kk << 9) + (p << 4)),
                  c + (size_t)((b << 8) + kc + kk) * 4096 + pxb + (p << 2));
        }
        if (needX) {
            #pragma unroll
            for (int i = 0; i < 4; i++) {
                int idx = tid + (i << 8);
                int kk = idx >> 5, p = idx & 31;
                cpa16(sb + OFF_STGX + (uint32_t)((kk << 9) + (p << 4)),
                      x + (size_t)((b << 8) + kc + kk) * 4096 + pxb + (p << 2));
            }
        }
        asm volatile("cp.async.commit_group;");
    };

    auto convert_one = [&](uint32_t stg, uint32_t dst16) {
        #pragma unroll
        for (int i = 0; i < 4; i++) {
            int idx = tid + (i << 8);
            int kk = idx >> 5, p = idx & 31;
            float4 v = *(const float4*)(smem + stg + (kk << 9) + (p << 4));
            __half2 h0 = __floats2half2_rn(v.x, v.y);
            __half2 h1 = __floats2half2_rn(v.z, v.w);
            *(uint2*)(smem + dst16 + swzB((uint32_t)((kk << 8) + (p << 3)))) =
                make_uint2(*(uint32_t*)&h0, *(uint32_t*)&h1);
        }
    };

    issue(0);

    for (int ck = 0; ck < 8; ck++) {
        asm volatile("cp.async.wait_group 0;");
        __syncthreads();                              // staging[ck] + A16[ck] visible
        const uint32_t sel = (uint32_t)((ck & 1) << 13);
        convert_one(OFF_STGC, OFF_B16C + sel);
        if (needX) convert_one(OFF_STGX, OFF_B16X + sel);
        __syncthreads();                              // B16[ck] ready; staging free
        if (ck < 7) issue(ck + 1);                    // overlaps compute below

        const uint32_t abuf = sb + OFF_A + sel;
        const uint32_t bbuf = sb + offB + sel;
        #pragma unroll
        for (int ks = 0; ks < 2; ks++) {
            uint32_t a[2][4], bf[8][2];
            #pragma unroll
            for (int mt = 0; mt < 2; mt++) {
                int row = (mw << 5) + (mt << 4) + (lane & 15);
                int kb  = (ks << 5) + ((lane >> 4) << 4);     // byte offset in 64B row
                ldsm_x4(a[mt], abuf + swzA((uint32_t)((row << 6) + kb)));
            }
            #pragma unroll
            for (int p = 0; p < 4; p++) {
                int krow = (ks << 4) + (lane & 15);
                int ncol = (nw << 6) + (p << 4) + ((lane >> 4) << 3);
                uint32_t r[4];
                ldsm_x4t(r, bbuf + swzB((uint32_t)((krow << 8) + (ncol << 1))));
                bf[2*p][0] = r[0]; bf[2*p][1] = r[1];
                bf[2*p+1][0] = r[2]; bf[2*p+1][1] = r[3];
            }
            #pragma unroll
            for (int mt = 0; mt < 2; mt++)
                #pragma unroll
                for (int nt = 0; nt < 8; nt++)
                    mma16816(d[mt][nt], a[mt], bf[nt]);
        }
    }

    // ================= epilogue =================
    const int g = lane >> 2, cc = lane & 3;
    const bool isK = (mblk == 2 && mw >= 2);          // channels 320-383

    #pragma unroll
    for (int mt = 0; mt < 2; mt++) {
        const int chA = ch0 + (mw << 5) + (mt << 4) + g;
        float* oA = out + ((size_t)b * 384 + chA) * 4096 + pxb + (nw << 6);
        float* oB = oA + (size_t)8 * 4096;
        if (!isK) {
            float s0 = g_bnsc[chA],     h0 = g_bnsh[chA];
            float s1 = g_bnsc[chA + 8], h1 = g_bnsh[chA + 8];
            #pragma unroll
            for (int nt = 0; nt < 8; nt++) {
                int col = (nt << 3) + (cc << 1);
                *(float2*)(oA + col) = make_float2(fmaf(d[mt][nt][0], s0, h0),
                                                   fmaf(d[mt][nt][1], s0, h0));
                *(float2*)(oB + col) = make_float2(fmaf(d[mt][nt][2], s1, h1),
                                                   fmaf(d[mt][nt][3], s1, h1));
            }
        } else {
            // softmax over this warp's 64 cols = one full W row (4-thread quad per row)
            float mx0 = -3.4e38f, mx1 = -3.4e38f;
            #pragma unroll
            for (int nt = 0; nt < 8; nt++) {
                mx0 = fmaxf(mx0, fmaxf(d[mt][nt][0], d[mt][nt][1]));
                mx1 = fmaxf(mx1, fmaxf(d[mt][nt][2], d[mt][nt][3]));
            }
            mx0 = fmaxf(mx0, __shfl_xor_sync(0xffffffffu, mx0, 1));
            mx0 = fmaxf(mx0, __shfl_xor_sync(0xffffffffu, mx0, 2));
            mx1 = fmaxf(mx1, __shfl_xor_sync(0xffffffffu, mx1, 1));
            mx1 = fmaxf(mx1, __shfl_xor_sync(0xffffffffu, mx1, 2));
            float s0 = 0.f, s1 = 0.f;
            #pragma unroll
            for (int nt = 0; nt < 8; nt++) {
                d[mt][nt][0] = __expf(d[mt][nt][0] - mx0); s0 += d[mt][nt][0];
                d[mt][nt][1] = __expf(d[mt][nt][1] - mx0); s0 += d[mt][nt][1];
                d[mt][nt][2] = __expf(d[mt][nt][2] - mx1); s1 += d[mt][nt][2];
                d[mt][nt][3] = __expf(d[mt][nt][3] - mx1); s1 += d[mt][nt][3];
            }
            s0 += __shfl_xor_sync(0xffffffffu, s0, 1);
            s0 += __shfl_xor_sync(0xffffffffu, s0, 2);
            s1 += __shfl_xor_sync(0xffffffffu, s1, 1);
            s1 += __shfl_xor_sync(0xffffffffu, s1, 2);
            float i0 = __frcp_rn(s0), i1 = __frcp_rn(s1);
            #pragma unroll
            for (int nt = 0; nt < 8; nt++) {
                int col = (nt << 3) + (cc << 1);
                *(float2*)(oA + col) = make_float2(d[mt][nt][0] * i0, d[mt][nt][1] * i0);
                *(float2*)(oB + col) = make_float2(d[mt][nt][2] * i1, d[mt][nt][3] * i1);
            }
        }
    }
}

extern "C" void kernel_launch(void* const* d_in, const int* in_sizes, int n_in,
                              void* d_out, int out_size)
{
    const float* x = (const float*)d_in[0];
    const float* c = (const float*)d_in[1];
    prep_kernel<<<96, 256>>>((const float*)d_in[2], (const float*)d_in[3],
                             (const float*)d_in[4], (const float*)d_in[5],
                             (const float*)d_in[6], (const float*)d_in[7],
                             (const float*)d_in[8], (const float*)d_in[9],
                             (const float*)d_in[10], (const float*)d_in[11],
                             (const float*)d_in[12]);
    cudaFuncSetAttribute(main_kernel, cudaFuncAttributeMaxDynamicSharedMemorySize, SMEM_TOTAL);
    main_kernel<<<3072, 256, SMEM_TOTAL>>>(x, c, (float*)d_out);
}

// round 7
// speedup vs baseline: 4.5706x; 1.0495x over previous
#include <cuda_runtime.h>
#include <cuda_fp16.h>
#include <cstdint>

#define EPS 1e-5f

__device__ __half g_Wh[384 * 256];
__device__ float g_bnsc[384];
__device__ float g_bnsh[384];

// smem byte offsets (K-chunk = 32)
#define OFF_A    0u        // A fp16: 2 bufs x 128 rows x 64B (swzA)   = 16 KB
#define OFF_B16X 16384u    // B fp16 x: 2 bufs x 32 rows x 256B       = 16 KB
#define OFF_B16C 32768u    // B fp16 c: 2 bufs x 32 rows x 256B       = 16 KB
#define OFF_STGX 49152u    // staging fp32 x: 2 bufs x 32 rows x 512B = 32 KB
#define OFF_STGC 81920u    // staging fp32 c: 2 bufs                  = 32 KB
#define SMEM_TOTAL 114688  // 112 KB -> 2 CTAs/SM

// 64B-row swizzle (A tiles)
__device__ __forceinline__ uint32_t swzA(uint32_t o) { return o ^ ((o >> 3) & 0x30); }
// 256B-row swizzle (B tiles)
__device__ __forceinline__ uint32_t swzB(uint32_t o) { return o ^ ((o >> 4) & 0x70); }

__device__ __forceinline__ uint32_t s2u(const void* p) {
    uint32_t a;
    asm("{ .reg .u64 t; cvta.to.shared.u64 t, %1; cvt.u32.u64 %0, t; }" : "=r"(a) : "l"(p));
    return a;
}
__device__ __forceinline__ void ldsm_x4(uint32_t* r, uint32_t a) {
    asm volatile("ldmatrix.sync.aligned.m8n8.x4.shared.b16 {%0,%1,%2,%3}, [%4];"
                 : "=r"(r[0]), "=r"(r[1]), "=r"(r[2]), "=r"(r[3]) : "r"(a));
}
__device__ __forceinline__ void ldsm_x4t(uint32_t* r, uint32_t a) {
    asm volatile("ldmatrix.sync.aligned.m8n8.x4.trans.shared.b16 {%0,%1,%2,%3}, [%4];"
                 : "=r"(r[0]), "=r"(r[1]), "=r"(r[2]), "=r"(r[3]) : "r"(a));
}
__device__ __forceinline__ void mma16816(float* d, const uint32_t* a, const uint32_t* b) {
    asm volatile("mma.sync.aligned.m16n8k16.row.col.f32.f16.f16.f32 "
                 "{%0,%1,%2,%3}, {%4,%5,%6,%7}, {%8,%9}, {%0,%1,%2,%3};"
                 : "+f"(d[0]), "+f"(d[1]), "+f"(d[2]), "+f"(d[3])
                 : "r"(a[0]), "r"(a[1]), "r"(a[2]), "r"(a[3]), "r"(b[0]), "r"(b[1]));
}
__device__ __forceinline__ void cpa16(uint32_t dst, const void* src) {
    asm volatile("cp.async.cg.shared.global [%0], [%1], 16;" :: "r"(dst), "l"(src));
}

// ---------------- prep: W fp32 -> fp16, fold BN ----------------
__global__ void prep_kernel(const float* __restrict__ Wq, const float* __restrict__ Wv,
                            const float* __restrict__ Wk,
                            const float* __restrict__ qg, const float* __restrict__ qb,
                            const float* __restrict__ qm, const float* __restrict__ qv,
                            const float* __restrict__ vg, const float* __restrict__ vb,
                            const float* __restrict__ vm, const float* __restrict__ vv)
{
    int idx = blockIdx.x * blockDim.x + threadIdx.x;
    int stride = gridDim.x * blockDim.x;
    for (int i = idx; i < 384 * 256; i += stride) {
        int r = i >> 8, k = i & 255;
        float w = (r < 64) ? Wq[(r << 8) | k]
                : (r < 320) ? Wv[((r - 64) << 8) | k]
                            : Wk[((r - 320) << 8) | k];
        g_Wh[i] = __float2half_rn(w);
    }
    if (idx < 384) {
        float sc = 1.f, sh = 0.f;
        if (idx < 320) {
            float g, b, m, v;
            if (idx < 64) { g = qg[idx]; b = qb[idx]; m = qm[idx]; v = qv[idx]; }
            else { g = vg[idx-64]; b = vb[idx-64]; m = vm[idx-64]; v = vv[idx-64]; }
            sc = g * rsqrtf(v + EPS);
            sh = b - m * sc;
        }
        g_bnsc[idx] = sc; g_bnsh[idx] = sh;
    }
}

// ---------------- main: pipelined fp16 HMMA GEMM ----------------
__global__ __launch_bounds__(256, 2)
void main_kernel(const float* __restrict__ x, const float* __restrict__ c,
                 float* __restrict__ out)
{
    extern __shared__ char smem[];
    const uint32_t sb = s2u(smem);
    const int tid = threadIdx.x, wid = tid >> 5, lane = tid & 31;
    const int mw = wid >> 1, nw = wid & 1;           // warp grid 4(M) x 2(N)
    const int bid = blockIdx.x;
    const int mblk = bid % 3;                        // ch blocks 0-127 / 128-255 / 256-383
    const int tile = bid / 3;
    const int b = tile >> 5, pxb = (tile & 31) << 7;
    const int ch0 = mblk << 7;

    float d[2][8][4];
    #pragma unroll
    for (int mt = 0; mt < 2; mt++)
        #pragma unroll
        for (int nt = 0; nt < 8; nt++)
            d[mt][nt][0] = d[mt][nt][1] = d[mt][nt][2] = d[mt][nt][3] = 0.f;

    const bool needX = (mblk == 0);
    // q channels (block0, mw<2) reduce over x; everything else over c
    const uint32_t offB = (mblk == 0 && mw < 2) ? OFF_B16X : OFF_B16C;

    // ---- async issue of chunk ck: A fp16 + fp32 staging of B (buf ck&1) ----
    auto issue = [&](int ck) {
        const int kc = ck << 5;
        const uint32_t sel13 = (uint32_t)((ck & 1) << 13);
        const uint32_t sel14 = (uint32_t)((ck & 1) << 14);
        #pragma unroll
        for (int i = 0; i < 2; i++) {                // A: 512 granules of 16B
            int idx = tid + (i << 8);
            int r = idx >> 2, u = idx & 3;
            cpa16(sb + OFF_A + sel13 + swzA((uint32_t)((r << 6) + (u << 4))),
                  g_Wh + ((ch0 + r) << 8) + kc + (u << 3));
        }
        #pragma unroll
        for (int i = 0; i < 4; i++) {                // staging c: 1024 granules
            int idx = tid + (i << 8);
            int kk = idx >> 5, p = idx & 31;
            cpa16(sb + OFF_STGC + sel14 + (uint32_t)((kk << 9) + (p << 4)),
                  c + (size_t)((b << 8) + kc + kk) * 4096 + pxb + (p << 2));
        }
        if (needX) {
            #pragma unroll
            for (int i = 0; i < 4; i++) {
                int idx = tid + (i << 8);
                int kk = idx >> 5, p = idx & 31;
                cpa16(sb + OFF_STGX + sel14 + (uint32_t)((kk << 9) + (p << 4)),
                      x + (size_t)((b << 8) + kc + kk) * 4096 + pxb + (p << 2));
            }
        }
        asm volatile("cp.async.commit_group;");
    };

    auto convert_one = [&](uint32_t stg, uint32_t dst16) {
        #pragma unroll
        for (int i = 0; i < 4; i++) {
            int idx = tid + (i << 8);
            int kk = idx >> 5, p = idx & 31;
            float4 v = *(const float4*)(smem + stg + (kk << 9) + (p << 4));
            __half2 h0 = __floats2half2_rn(v.x, v.y);
            __half2 h1 = __floats2half2_rn(v.z, v.w);
            *(uint2*)(smem + dst16 + swzB((uint32_t)((kk << 8) + (p << 3)))) =
                make_uint2(*(uint32_t*)&h0, *(uint32_t*)&h1);
        }
    };

    issue(0);

    for (int ck = 0; ck < 8; ck++) {
        asm volatile("cp.async.wait_group 0;");       // chunk ck landed
        __syncthreads();                              // + everyone done with prev bufs
        if (ck < 7) issue(ck + 1);                    // overlaps convert+compute below
        const uint32_t sel13 = (uint32_t)((ck & 1) << 13);
        const uint32_t sel14 = (uint32_t)((ck & 1) << 14);
        convert_one(OFF_STGC + sel14, OFF_B16C + sel13);
        if (needX) convert_one(OFF_STGX + sel14, OFF_B16X + sel13);
        __syncthreads();                              // B16[ck] ready

        const uint32_t abuf = sb + OFF_A + sel13;
        const uint32_t bbuf = sb + offB + sel13;
        #pragma unroll
        for (int ks = 0; ks < 2; ks++) {
            uint32_t a[2][4], bf[8][2];
            #pragma unroll
            for (int mt = 0; mt < 2; mt++) {
                int row = (mw << 5) + (mt << 4) + (lane & 15);
                int kb  = (ks << 5) + ((lane >> 4) << 4);     // byte offset in 64B row
                ldsm_x4(a[mt], abuf + swzA((uint32_t)((row << 6) + kb)));
            }
            #pragma unroll
            for (int p = 0; p < 4; p++) {
                int krow = (ks << 4) + (lane & 15);
                int ncol = (nw << 6) + (p << 4) + ((lane >> 4) << 3);
                uint32_t r[4];
                ldsm_x4t(r, bbuf + swzB((uint32_t)((krow << 8) + (ncol << 1))));
                bf[2*p][0] = r[0]; bf[2*p][1] = r[1];
                bf[2*p+1][0] = r[2]; bf[2*p+1][1] = r[3];
            }
            #pragma unroll
            for (int mt = 0; mt < 2; mt++)
                #pragma unroll
                for (int nt = 0; nt < 8; nt++)
                    mma16816(d[mt][nt], a[mt], bf[nt]);
        }
    }

    // ================= epilogue =================
    const int g = lane >> 2, cc = lane & 3;
    const bool isK = (mblk == 2 && mw >= 2);          // channels 320-383

    #pragma unroll
    for (int mt = 0; mt < 2; mt++) {
        const int chA = ch0 + (mw << 5) + (mt << 4) + g;
        float* oA = out + ((size_t)b * 384 + chA) * 4096 + pxb + (nw << 6);
        float* oB = oA + (size_t)8 * 4096;
        if (!isK) {
            float s0 = g_bnsc[chA],     h0 = g_bnsh[chA];
            float s1 = g_bnsc[chA + 8], h1 = g_bnsh[chA + 8];
            #pragma unroll
            for (int nt = 0; nt < 8; nt++) {
                int col = (nt << 3) + (cc << 1);
                *(float2*)(oA + col) = make_float2(fmaf(d[mt][nt][0], s0, h0),
                                                   fmaf(d[mt][nt][1], s0, h0));
                *(float2*)(oB + col) = make_float2(fmaf(d[mt][nt][2], s1, h1),
                                                   fmaf(d[mt][nt][3], s1, h1));
            }
        } else {
            // softmax over this warp's 64 cols = one full W row (4-thread quad per row)
            float mx0 = -3.4e38f, mx1 = -3.4e38f;
            #pragma unroll
            for (int nt = 0; nt < 8; nt++) {
                mx0 = fmaxf(mx0, fmaxf(d[mt][nt][0], d[mt][nt][1]));
                mx1 = fmaxf(mx1, fmaxf(d[mt][nt][2], d[mt][nt][3]));
            }
            mx0 = fmaxf(mx0, __shfl_xor_sync(0xffffffffu, mx0, 1));
            mx0 = fmaxf(mx0, __shfl_xor_sync(0xffffffffu, mx0, 2));
            mx1 = fmaxf(mx1, __shfl_xor_sync(0xffffffffu, mx1, 1));
            mx1 = fmaxf(mx1, __shfl_xor_sync(0xffffffffu, mx1, 2));
            float s0 = 0.f, s1 = 0.f;
            #pragma unroll
            for (int nt = 0; nt < 8; nt++) {
                d[mt][nt][0] = __expf(d[mt][nt][0] - mx0); s0 += d[mt][nt][0];
                d[mt][nt][1] = __expf(d[mt][nt][1] - mx0); s0 += d[mt][nt][1];
                d[mt][nt][2] = __expf(d[mt][nt][2] - mx1); s1 += d[mt][nt][2];
                d[mt][nt][3] = __expf(d[mt][nt][3] - mx1); s1 += d[mt][nt][3];
            }
            s0 += __shfl_xor_sync(0xffffffffu, s0, 1);
            s0 += __shfl_xor_sync(0xffffffffu, s0, 2);
            s1 += __shfl_xor_sync(0xffffffffu, s1, 1);
            s1 += __shfl_xor_sync(0xffffffffu, s1, 2);
            float i0 = __frcp_rn(s0), i1 = __frcp_rn(s1);
            #pragma unroll
            for (int nt = 0; nt < 8; nt++) {
                int col = (nt << 3) + (cc << 1);
                *(float2*)(oA + col) = make_float2(d[mt][nt][0] * i0, d[mt][nt][1] * i0);
                *(float2*)(oB + col) = make_float2(d[mt][nt][2] * i1, d[mt][nt][3] * i1);
            }
        }
    }
}

extern "C" void kernel_launch(void* const* d_in, const int* in_sizes, int n_in,
                              void* d_out, int out_size)
{
    const float* x = (const float*)d_in[0];
    const float* c = (const float*)d_in[1];
    prep_kernel<<<96, 256>>>((const float*)d_in[2], (const float*)d_in[3],
                             (const float*)d_in[4], (const float*)d_in[5],
                             (const float*)d_in[6], (const float*)d_in[7],
                             (const float*)d_in[8], (const float*)d_in[9],
                             (const float*)d_in[10], (const float*)d_in[11],
                             (const float*)d_in[12]);
    cudaFuncSetAttribute(main_kernel, cudaFuncAttributeMaxDynamicSharedMemorySize, SMEM_TOTAL);
    main_kernel<<<3072, 256, SMEM_TOTAL>>>(x, c, (float*)d_out);
}